// round 14
// baseline (speedup 1.0000x reference)
#include <cuda_runtime.h>

#define T_STEPS 2000
#define N_IN    8192
#define N_OUT   4096

__device__ float g_lif[(size_t)T_STEPS * N_OUT];
__device__ int   g_flags[32];

constexpr int BM = 64, BN = 128, BK = 8, TM = 8, TN = 8;
constexpr int M_BLK = 32, N_BLK = 32;    // 1024 tiles

__global__ void zero_flags_kernel() {
    if (threadIdx.x < M_BLK) g_flags[threadIdx.x] = 0;
}

__device__ __forceinline__ int ld_acquire_gpu(const int* p) {
    int v;
    asm volatile("ld.acquire.gpu.s32 %0, [%1];" : "=r"(v) : "l"(p) : "memory");
    return v;
}

// ---------------------------------------------------------------------------
// GEMM — 64x128 tiles, 128 threads, 8x8 micro-tile: inner loop instruction
// pattern and per-output ascending-k fp32 fma chain identical to R1 (bit-exact).
// 1024 tiles -> per-SM granularity 7/6.92 = 98.8% (vs 4/3.46 = 86.5%).
// ---------------------------------------------------------------------------
__global__ __launch_bounds__(128, 4)
void gemm_nt_kernel(const float* __restrict__ A,   // [M,K]
                    const float* __restrict__ B,   // [N,K]
                    float* __restrict__ C,         // [M,N]
                    int M, int N, int K)
{
    __shared__ float As[2][BK][BM];   // 4 KB
    __shared__ float Bs[2][BK][BN];   // 8 KB

    const int tid = threadIdx.x;
    const int bm  = blockIdx.y * BM;
    const int bn  = blockIdx.x * BN;

    // A loader: 64 rows x 8k = 128 float4, one per thread
    const int aRow = tid >> 1;            // 0..63
    const int aCol = (tid & 1) * 4;       // 0 or 4
    // B loader: 128 rows x 8k = 256 float4, two per thread (row tid, k 0..7)
    const int bRow = tid;                 // 0..127

    // compute: 8(m) x 16(n) thread grid, micro-tile 8x8 (same as R1)
    const int tr = (tid >> 4) * TM;       // 0..56
    const int tc = (tid & 15) * TN;       // 0..120

    float acc[TM][TN];
    #pragma unroll
    for (int i = 0; i < TM; i++)
        #pragma unroll
        for (int j = 0; j < TN; j++)
            acc[i][j] = 0.0f;

    const bool aValid = (bm + aRow) < M;
    const float* Aptr = A + (size_t)(bm + aRow) * K + aCol;
    const float* Bptr = B + (size_t)(bn + bRow) * K;

    // stage chunk 0
    float4 a4 = aValid ? *(const float4*)(Aptr) : make_float4(0.f, 0.f, 0.f, 0.f);
    float4 b40 = *(const float4*)(Bptr);
    float4 b41 = *(const float4*)(Bptr + 4);

    int s = 0;
    for (int k0 = 0; k0 < K; k0 += BK) {
        As[s][aCol + 0][aRow] = a4.x;
        As[s][aCol + 1][aRow] = a4.y;
        As[s][aCol + 2][aRow] = a4.z;
        As[s][aCol + 3][aRow] = a4.w;
        Bs[s][0][bRow] = b40.x;
        Bs[s][1][bRow] = b40.y;
        Bs[s][2][bRow] = b40.z;
        Bs[s][3][bRow] = b40.w;
        Bs[s][4][bRow] = b41.x;
        Bs[s][5][bRow] = b41.y;
        Bs[s][6][bRow] = b41.z;
        Bs[s][7][bRow] = b41.w;
        __syncthreads();

        if (k0 + BK < K) {
            a4 = aValid ? *(const float4*)(Aptr + k0 + BK)
                        : make_float4(0.f, 0.f, 0.f, 0.f);
            b40 = *(const float4*)(Bptr + k0 + BK);
            b41 = *(const float4*)(Bptr + k0 + BK + 4);
        }

        #pragma unroll
        for (int k = 0; k < BK; k++) {
            float ar[TM], br[TN];
            #pragma unroll
            for (int i = 0; i < TM; i++) ar[i] = As[s][k][tr + i];
            #pragma unroll
            for (int j = 0; j < TN; j++) br[j] = Bs[s][k][tc + j];
            #pragma unroll
            for (int i = 0; i < TM; i++)
                #pragma unroll
                for (int j = 0; j < TN; j++)
                    acc[i][j] += ar[i] * br[j];   // ascending-k fma chain
        }
        s ^= 1;
    }

    #pragma unroll
    for (int i = 0; i < TM; i++) {
        int gm = bm + tr + i;
        if (gm < M) {
            float* Crow = C + (size_t)gm * N + bn + tc;
            #pragma unroll
            for (int j = 0; j < TN; j += 4) {
                float4 v = make_float4(acc[i][j], acc[i][j+1],
                                       acc[i][j+2], acc[i][j+3]);
                *(float4*)(Crow + j) = v;
            }
        }
    }

    __threadfence();
    __syncthreads();
    if (tid == 0) atomicAdd(&g_flags[blockIdx.y], 1);
}

// ---------------------------------------------------------------------------
// LIF scan — R13's overlapped consumer (rel_err 0.0), m-blocks now 64 steps.
// ---------------------------------------------------------------------------
__device__ __forceinline__ float lif_step(float inp, float& v, float& refrac,
                                          float dt_tau, float rest, float th,
                                          float rst, float trf)
{
    const float DT = 0.001f;
    float v1 = v - dt_tau * (v - rest);
    float va = v1 + inp;
    v1 = (refrac == 0.0f) ? va : v1;
    float rf = refrac - DT;
    rf = (refrac > 0.0f) ? rf : 0.0f;
    bool p = (v1 >= th);
    float spike = p ? 1.0f : 0.0f;
    refrac = p ? trf : rf;
    v = p ? rst : v1;
    return spike;
}

__global__ __launch_bounds__(32)
void lif_scan_kernel(const float* __restrict__ lif,
                     float* __restrict__ out,
                     const float* __restrict__ v_th,
                     const float* __restrict__ v_rest,
                     const float* __restrict__ v_reset,
                     const float* __restrict__ t_ref,
                     const float* __restrict__ tau)
{
    const int n = blockIdx.x * 32 + threadIdx.x;   // 128*32 = 4096

    const float th   = v_th[n];
    const float rest = v_rest[n];
    const float rst  = v_reset[n];
    const float trf  = t_ref[n];
    const float dt_tau = 0.001f * tau[n];

    float v = rest;
    float refrac = 0.0f;
    out[n] = 0.0f;

    for (int b = 0; b < M_BLK; b++) {
        const int t0 = (b == 0) ? 1 : b * BM;
        const int t1 = (b + 1) * BM < T_STEPS ? (b + 1) * BM : T_STEPS;
        if (t0 >= t1) break;

        while (ld_acquire_gpu(&g_flags[b]) < N_BLK) __nanosleep(128);
        __syncwarp();

        int t = t0;
        while (t + 16 <= t1) {
            float buf[16];
            #pragma unroll
            for (int j = 0; j < 16; j++)
                buf[j] = lif[(size_t)(t + j) * N_OUT + n];
            #pragma unroll
            for (int j = 0; j < 16; j++)
                out[(size_t)(t + j) * N_OUT + n] =
                    lif_step(buf[j], v, refrac, dt_tau, rest, th, rst, trf);
            t += 16;
        }
        while (t < t1) {
            float inp = lif[(size_t)t * N_OUT + n];
            out[(size_t)t * N_OUT + n] =
                lif_step(inp, v, refrac, dt_tau, rest, th, rst, trf);
            t++;
        }
    }
}

// ---------------------------------------------------------------------------
extern "C" void kernel_launch(void* const* d_in, const int* in_sizes, int n_in,
                              void* d_out, int out_size)
{
    const float* x       = (const float*)d_in[0];
    const float* weight  = (const float*)d_in[1];
    const float* v_th    = (const float*)d_in[2];
    const float* v_rest  = (const float*)d_in[3];
    const float* v_reset = (const float*)d_in[4];
    const float* t_ref   = (const float*)d_in[5];
    const float* tau     = (const float*)d_in[6];
    float* out = (float*)d_out;

    float* lif_ptr = nullptr;
    cudaGetSymbolAddress((void**)&lif_ptr, g_lif);

    cudaStream_t s2;
    cudaEvent_t ev0, ev1;
    cudaStreamCreateWithFlags(&s2, cudaStreamNonBlocking);
    cudaEventCreateWithFlags(&ev0, cudaEventDisableTiming);
    cudaEventCreateWithFlags(&ev1, cudaEventDisableTiming);

    zero_flags_kernel<<<1, 32>>>();
    cudaEventRecord(ev0, 0);
    cudaStreamWaitEvent(s2, ev0, 0);

    // producer: 32 x 32 = 1024 tiles of 64x128
    dim3 grid(N_OUT / BN, M_BLK);
    gemm_nt_kernel<<<grid, 128>>>(x, weight, lif_ptr, T_STEPS, N_OUT, N_IN);

    // consumer: overlapped scan
    lif_scan_kernel<<<128, 32, 0, s2>>>(lif_ptr, out,
                                        v_th, v_rest, v_reset, t_ref, tau);

    cudaEventRecord(ev1, s2);
    cudaStreamWaitEvent(0, ev1, 0);
}